// round 3
// baseline (speedup 1.0000x reference)
#include <cuda_runtime.h>
#include <cuda_bf16.h>

// ---------------------------------------------------------------------------
// SSIM (11x11 Gaussian, sigma=1.5, SAME zero padding) over 32x3x512x512 fp32.
// Strategy: separable conv, per-tile fused pipeline, deterministic reduction.
// ---------------------------------------------------------------------------

#define IMG_H 512
#define IMG_W 512
#define N_PLANES 96          // 32 * 3
#define TILE 32
#define HALO 5
#define LOAD 42              // TILE + 2*HALO
#define PITCH 44             // LOAD padded to multiple of 4 (16B float4 align)
#define NBLK_X (IMG_W / TILE)   // 16
#define NBLK_Y (IMG_H / TILE)   // 16
#define NPART (NBLK_X * NBLK_Y * N_PLANES)  // 24576
#define NPIX (32.0 * 3.0 * 512.0 * 512.0)   // 25165824

#define C1F 0.0001f          // (0.01)^2
#define C2F 0.0009f          // (0.03)^2

// Gaussian taps: g[i] = exp(-d^2/4.5), d = i-5, normalized. __device__
// constexpr so device code sees them as compile-time constants -> ptxas
// emits FFMA-imm (rt=1 per SMSP, 2x normal FFMA rate).
__device__ constexpr double G0 = 0.003865920;   // exp(-25/4.5)
__device__ constexpr double G1 = 0.028565467;   // exp(-16/4.5)
__device__ constexpr double G2 = 0.135335283;   // exp(-9/4.5)
__device__ constexpr double G3 = 0.411111966;   // exp(-4/4.5)
__device__ constexpr double G4 = 0.800737403;   // exp(-1/4.5)
__device__ constexpr double G5 = 1.0;
__device__ constexpr double GS = G5 + 2.0 * (G0 + G1 + G2 + G3 + G4);
__device__ constexpr float W11[11] = {
    (float)(G0 / GS), (float)(G1 / GS), (float)(G2 / GS), (float)(G3 / GS),
    (float)(G4 / GS), (float)(G5 / GS), (float)(G4 / GS), (float)(G3 / GS),
    (float)(G2 / GS), (float)(G1 / GS), (float)(G0 / GS)};

__device__ float g_partial[NPART];

#define SMEM_Q_FLOATS (5 * LOAD * PITCH)   // 5 * 42 * 44 = 9240
#define SMEM_H_FLOATS (5 * LOAD * TILE)    // 5 * 42 * 32 = 6720
#define SMEM_BYTES ((SMEM_Q_FLOATS + SMEM_H_FLOATS) * 4)  // 63840 B

__global__ __launch_bounds__(256) void ssim_tile_kernel(
    const float* __restrict__ img1, const float* __restrict__ img2)
{
    extern __shared__ float smem[];
    float* Q = smem;                       // [5][LOAD][PITCH]
    float* H = smem + SMEM_Q_FLOATS;       // [5][LOAD][TILE]
    __shared__ float red[256];

#define QQ(q, r, c) Q[((q) * LOAD + (r)) * PITCH + (c)]
#define HH(q, r, c) H[((q) * LOAD + (r)) * TILE + (c)]

    const int tid = threadIdx.x;
    const int plane = blockIdx.z;
    const int ty0 = blockIdx.y * TILE - HALO;
    const int tx0 = blockIdx.x * TILE - HALO;
    const float* p1 = img1 + (size_t)plane * IMG_H * IMG_W;
    const float* p2 = img2 + (size_t)plane * IMG_H * IMG_W;

    // ---- Stage 1: load halo tile, form the 5 moment inputs ----
    for (int i = tid; i < LOAD * LOAD; i += 256) {
        int r = i / LOAD, c = i - r * LOAD;
        int gy = ty0 + r, gx = tx0 + c;
        float a = 0.f, b = 0.f;
        if (gy >= 0 && gy < IMG_H && gx >= 0 && gx < IMG_W) {
            int gidx = gy * IMG_W + gx;
            a = p1[gidx];
            b = p2[gidx];
        }
        QQ(0, r, c) = a;
        QQ(1, r, c) = b;
        QQ(2, r, c) = a * a;
        QQ(3, r, c) = b * b;
        QQ(4, r, c) = a * b;
    }
    __syncthreads();

    // ---- Stage 2: horizontal 11-tap pass, 4-col register blocking ----
    // 42 rows x 8 col-groups = 336 groups; each group produces 4 outputs/qty.
    for (int gi = tid; gi < LOAD * 8; gi += 256) {
        int r = gi >> 3;
        int c0 = (gi & 7) * 4;     // output cols c0..c0+3, needs input c0..c0+13
#pragma unroll
        for (int qi = 0; qi < 5; qi++) {
            float v[16];
            const float4* src = (const float4*)&QQ(qi, r, c0);  // 16B aligned
#pragma unroll
            for (int t = 0; t < 4; t++) {
                float4 f = src[t];
                v[4 * t + 0] = f.x; v[4 * t + 1] = f.y;
                v[4 * t + 2] = f.z; v[4 * t + 3] = f.w;
            }
            float acc0 = 0.f, acc1 = 0.f, acc2 = 0.f, acc3 = 0.f;
#pragma unroll
            for (int k = 0; k < 11; k++) {
                acc0 = fmaf(W11[k], v[k + 0], acc0);
                acc1 = fmaf(W11[k], v[k + 1], acc1);
                acc2 = fmaf(W11[k], v[k + 2], acc2);
                acc3 = fmaf(W11[k], v[k + 3], acc3);
            }
            HH(qi, r, c0 + 0) = acc0;
            HH(qi, r, c0 + 1) = acc1;
            HH(qi, r, c0 + 2) = acc2;
            HH(qi, r, c0 + 3) = acc3;
        }
    }
    __syncthreads();

    // ---- Stage 3: vertical 11-tap pass, 4-row register blocking + epilogue ----
    // 256 threads == 32 cols x 8 row-groups, each group = 4 output rows.
    const int c = tid & 31;
    const int r0 = (tid >> 5) * 4;     // output rows r0..r0+3, input rows r0..r0+13
    float acc[5][4];
#pragma unroll
    for (int qi = 0; qi < 5; qi++)
#pragma unroll
        for (int j = 0; j < 4; j++) acc[qi][j] = 0.f;

#pragma unroll
    for (int k = 0; k < 14; k++) {
        float v[5];
#pragma unroll
        for (int qi = 0; qi < 5; qi++) v[qi] = HH(qi, r0 + k, c);
#pragma unroll
        for (int j = 0; j < 4; j++) {
            const int wi = k - j;
            if (wi >= 0 && wi < 11) {
#pragma unroll
                for (int qi = 0; qi < 5; qi++)
                    acc[qi][j] = fmaf(W11[wi], v[qi], acc[qi][j]);
            }
        }
    }

    float local = 0.f;
#pragma unroll
    for (int j = 0; j < 4; j++) {
        float mu1 = acc[0][j], mu2 = acc[1][j];
        float ex2 = acc[2][j], ey2 = acc[3][j], exy = acc[4][j];
        float mu1s = mu1 * mu1, mu2s = mu2 * mu2, mu12 = mu1 * mu2;
        float s1q = fmaxf(ex2 - mu1s, 0.f);
        float s2q = fmaxf(ey2 - mu2s, 0.f);
        float s12 = exy - mu12;
        float sp = sqrtf(s1q * s2q);         // == s1*s2
        float num = (2.f * mu12 + C1F) * (2.f * sp + C2F) * (s12 + 0.5f * C2F);
        float den = (mu1s + mu2s + C1F) * (s1q + s2q + C2F) * (sp + 0.5f * C2F);
        local += __fdividef(num, den);
    }

    // ---- Block reduction (fixed-order tree: deterministic) ----
    red[tid] = local;
    __syncthreads();
#pragma unroll
    for (int s = 128; s > 0; s >>= 1) {
        if (tid < s) red[tid] += red[tid + s];
        __syncthreads();
    }
    if (tid == 0) {
        int bid = (blockIdx.z * NBLK_Y + blockIdx.y) * NBLK_X + blockIdx.x;
        g_partial[bid] = red[0];
    }
#undef QQ
#undef HH
}

__global__ __launch_bounds__(256) void ssim_reduce_kernel(float* __restrict__ out)
{
    __shared__ double red[256];
    const int tid = threadIdx.x;
    double s = 0.0;
    for (int i = tid; i < NPART; i += 256) s += (double)g_partial[i];
    red[tid] = s;
    __syncthreads();
#pragma unroll
    for (int st = 128; st > 0; st >>= 1) {
        if (tid < st) red[tid] += red[tid + st];
        __syncthreads();
    }
    if (tid == 0) out[0] = (float)(red[0] / NPIX);
}

extern "C" void kernel_launch(void* const* d_in, const int* in_sizes, int n_in,
                              void* d_out, int out_size)
{
    const float* img1 = (const float*)d_in[0];
    const float* img2 = (const float*)d_in[1];
    // d_in[2] (window) unused: taps are baked in as compile-time constants.
    float* out = (float*)d_out;

    static bool attr_done = false;
    if (!attr_done) {
        cudaFuncSetAttribute(ssim_tile_kernel,
                             cudaFuncAttributeMaxDynamicSharedMemorySize,
                             SMEM_BYTES);
        attr_done = true;
    }

    dim3 grid(NBLK_X, NBLK_Y, N_PLANES);
    ssim_tile_kernel<<<grid, 256, SMEM_BYTES>>>(img1, img2);
    ssim_reduce_kernel<<<1, 256>>>(out);
}

// round 4
// speedup vs baseline: 1.3783x; 1.3783x over previous
#include <cuda_runtime.h>
#include <cuda_bf16.h>

// ---------------------------------------------------------------------------
// SSIM (11x11 Gaussian, sigma=1.5, SAME zero padding) over 32x3x512x512 fp32.
// Separable conv, per-tile fused pipeline, deterministic two-stage reduction.
// R3: Q holds only (a,b); moments computed in registers during the horizontal
// pass (cuts smem crossbar traffic ~35%, occupancy 3->5 CTA/SM).
// ---------------------------------------------------------------------------

#define IMG_H 512
#define IMG_W 512
#define N_PLANES 96          // 32 * 3
#define TILE 32
#define HALO 5
#define LOAD 42              // TILE + 2*HALO
#define PITCH 44             // LOAD padded for 16B float4 alignment
#define NBLK_X (IMG_W / TILE)   // 16
#define NBLK_Y (IMG_H / TILE)   // 16
#define NPART (NBLK_X * NBLK_Y * N_PLANES)  // 24576
#define NPART2 96
#define NPIX (32.0 * 3.0 * 512.0 * 512.0)   // 25165824

#define C1F 0.0001f          // (0.01)^2
#define C2F 0.0009f          // (0.03)^2

// Gaussian taps as compile-time constants -> FFMA-imm in SASS.
__device__ constexpr double G0 = 0.003865920;   // exp(-25/4.5)
__device__ constexpr double G1 = 0.028565467;   // exp(-16/4.5)
__device__ constexpr double G2 = 0.135335283;   // exp(-9/4.5)
__device__ constexpr double G3 = 0.411111966;   // exp(-4/4.5)
__device__ constexpr double G4 = 0.800737403;   // exp(-1/4.5)
__device__ constexpr double G5 = 1.0;
__device__ constexpr double GS = G5 + 2.0 * (G0 + G1 + G2 + G3 + G4);
__device__ constexpr float W11[11] = {
    (float)(G0 / GS), (float)(G1 / GS), (float)(G2 / GS), (float)(G3 / GS),
    (float)(G4 / GS), (float)(G5 / GS), (float)(G4 / GS), (float)(G3 / GS),
    (float)(G2 / GS), (float)(G1 / GS), (float)(G0 / GS)};

__device__ float g_partial[NPART];
__device__ float g_partial2[NPART2];

#define SMEM_Q_FLOATS (2 * LOAD * PITCH)   // 2 * 42 * 44 = 3696
#define SMEM_H_FLOATS (5 * LOAD * TILE)    // 5 * 42 * 32 = 6720
#define SMEM_BYTES ((SMEM_Q_FLOATS + SMEM_H_FLOATS) * 4)  // 41664 B

__global__ __launch_bounds__(256) void ssim_tile_kernel(
    const float* __restrict__ img1, const float* __restrict__ img2)
{
    extern __shared__ float smem[];
    float* Q = smem;                       // [2][LOAD][PITCH]  (a, b)
    float* H = smem + SMEM_Q_FLOATS;       // [5][LOAD][TILE]   (h-convolved moments)
    __shared__ float red[256];

#define QQ(q, r, c) Q[((q) * LOAD + (r)) * PITCH + (c)]
#define HH(q, r, c) H[((q) * LOAD + (r)) * TILE + (c)]

    const int tid = threadIdx.x;
    const int plane = blockIdx.z;
    const int ty0 = blockIdx.y * TILE - HALO;
    const int tx0 = blockIdx.x * TILE - HALO;
    const float* p1 = img1 + (size_t)plane * IMG_H * IMG_W;
    const float* p2 = img2 + (size_t)plane * IMG_H * IMG_W;

    // ---- Stage 1: load halo tile (zero padded) ----
    for (int i = tid; i < LOAD * LOAD; i += 256) {
        int r = i / LOAD, c = i - r * LOAD;
        int gy = ty0 + r, gx = tx0 + c;
        float a = 0.f, b = 0.f;
        if (gy >= 0 && gy < IMG_H && gx >= 0 && gx < IMG_W) {
            int gidx = gy * IMG_W + gx;
            a = p1[gidx];
            b = p2[gidx];
        }
        QQ(0, r, c) = a;
        QQ(1, r, c) = b;
    }
    __syncthreads();

    // ---- Stage 2: horizontal 11-tap pass over 5 moments, 4-col blocking ----
    // Moments (a*a, b*b, a*b) formed in registers from a,b; never hit smem raw.
    for (int gi = tid; gi < LOAD * 8; gi += 256) {
        int r = gi >> 3;
        int c0 = (gi & 7) * 4;     // outputs c0..c0+3 need inputs c0..c0+13
        float av[16], bv[16];
        {
            const float4* sa = (const float4*)&QQ(0, r, c0);
            const float4* sb = (const float4*)&QQ(1, r, c0);
#pragma unroll
            for (int t = 0; t < 4; t++) {
                float4 fa = sa[t], fb = sb[t];
                av[4 * t + 0] = fa.x; av[4 * t + 1] = fa.y;
                av[4 * t + 2] = fa.z; av[4 * t + 3] = fa.w;
                bv[4 * t + 0] = fb.x; bv[4 * t + 1] = fb.y;
                bv[4 * t + 2] = fb.z; bv[4 * t + 3] = fb.w;
            }
        }
        float acc[5][4];
#pragma unroll
        for (int qi = 0; qi < 5; qi++)
#pragma unroll
            for (int j = 0; j < 4; j++) acc[qi][j] = 0.f;

#pragma unroll
        for (int k = 0; k < 14; k++) {
            float a = av[k], b = bv[k];
            float aa = a * a, bb = b * b, ab = a * b;
#pragma unroll
            for (int j = 0; j < 4; j++) {
                const int wi = k - j;
                if (wi >= 0 && wi < 11) {
                    acc[0][j] = fmaf(W11[wi], a,  acc[0][j]);
                    acc[1][j] = fmaf(W11[wi], b,  acc[1][j]);
                    acc[2][j] = fmaf(W11[wi], aa, acc[2][j]);
                    acc[3][j] = fmaf(W11[wi], bb, acc[3][j]);
                    acc[4][j] = fmaf(W11[wi], ab, acc[4][j]);
                }
            }
        }
#pragma unroll
        for (int qi = 0; qi < 5; qi++)
#pragma unroll
            for (int j = 0; j < 4; j++)
                HH(qi, r, c0 + j) = acc[qi][j];
    }
    __syncthreads();

    // ---- Stage 3: vertical 11-tap pass, 4-row blocking + fused epilogue ----
    const int c = tid & 31;
    const int r0 = (tid >> 5) * 4;     // output rows r0..r0+3, inputs r0..r0+13
    float acc[5][4];
#pragma unroll
    for (int qi = 0; qi < 5; qi++)
#pragma unroll
        for (int j = 0; j < 4; j++) acc[qi][j] = 0.f;

#pragma unroll
    for (int k = 0; k < 14; k++) {
        float v[5];
#pragma unroll
        for (int qi = 0; qi < 5; qi++) v[qi] = HH(qi, r0 + k, c);
#pragma unroll
        for (int j = 0; j < 4; j++) {
            const int wi = k - j;
            if (wi >= 0 && wi < 11) {
#pragma unroll
                for (int qi = 0; qi < 5; qi++)
                    acc[qi][j] = fmaf(W11[wi], v[qi], acc[qi][j]);
            }
        }
    }

    float local = 0.f;
#pragma unroll
    for (int j = 0; j < 4; j++) {
        float mu1 = acc[0][j], mu2 = acc[1][j];
        float ex2 = acc[2][j], ey2 = acc[3][j], exy = acc[4][j];
        float mu1s = mu1 * mu1, mu2s = mu2 * mu2, mu12 = mu1 * mu2;
        float s1q = fmaxf(ex2 - mu1s, 0.f);
        float s2q = fmaxf(ey2 - mu2s, 0.f);
        float s12 = exy - mu12;
        float sp = sqrtf(s1q * s2q);         // == s1*s2
        float num = (2.f * mu12 + C1F) * (2.f * sp + C2F) * (s12 + 0.5f * C2F);
        float den = (mu1s + mu2s + C1F) * (s1q + s2q + C2F) * (sp + 0.5f * C2F);
        local += __fdividef(num, den);
    }

    // ---- Block reduction (fixed-order tree: deterministic) ----
    red[tid] = local;
    __syncthreads();
#pragma unroll
    for (int s = 128; s > 0; s >>= 1) {
        if (tid < s) red[tid] += red[tid + s];
        __syncthreads();
    }
    if (tid == 0) {
        int bid = (blockIdx.z * NBLK_Y + blockIdx.y) * NBLK_X + blockIdx.x;
        g_partial[bid] = red[0];
    }
#undef QQ
#undef HH
}

// Stage A: 96 blocks, each sums 256 contiguous partials (deterministic tree).
__global__ __launch_bounds__(256) void ssim_reduceA_kernel()
{
    __shared__ float red[256];
    const int tid = threadIdx.x;
    red[tid] = g_partial[blockIdx.x * 256 + tid];
    __syncthreads();
#pragma unroll
    for (int s = 128; s > 0; s >>= 1) {
        if (tid < s) red[tid] += red[tid + s];
        __syncthreads();
    }
    if (tid == 0) g_partial2[blockIdx.x] = red[0];
}

// Stage B: single block sums 96 values in double, normalizes.
__global__ __launch_bounds__(128) void ssim_reduceB_kernel(float* __restrict__ out)
{
    __shared__ double red[128];
    const int tid = threadIdx.x;
    red[tid] = (tid < NPART2) ? (double)g_partial2[tid] : 0.0;
    __syncthreads();
#pragma unroll
    for (int st = 64; st > 0; st >>= 1) {
        if (tid < st) red[tid] += red[tid + st];
        __syncthreads();
    }
    if (tid == 0) out[0] = (float)(red[0] / NPIX);
}

extern "C" void kernel_launch(void* const* d_in, const int* in_sizes, int n_in,
                              void* d_out, int out_size)
{
    const float* img1 = (const float*)d_in[0];
    const float* img2 = (const float*)d_in[1];
    // d_in[2] (window) unused: taps baked in as compile-time constants.
    float* out = (float*)d_out;

    static bool attr_done = false;
    if (!attr_done) {
        cudaFuncSetAttribute(ssim_tile_kernel,
                             cudaFuncAttributeMaxDynamicSharedMemorySize,
                             SMEM_BYTES);
        attr_done = true;
    }

    dim3 grid(NBLK_X, NBLK_Y, N_PLANES);
    ssim_tile_kernel<<<grid, 256, SMEM_BYTES>>>(img1, img2);
    ssim_reduceA_kernel<<<NPART2, 256>>>();
    ssim_reduceB_kernel<<<1, 128>>>(out);
}